// round 1
// baseline (speedup 1.0000x reference)
#include <cuda_runtime.h>
#include <math_constants.h>
#include <cstdint>

// Problem constants (fixed shapes per reference setup_inputs)
#define BB 16      // batch
#define SS 512     // seq len
#define DD 256     // model dim
#define HH 16      // heads
#define HD 16      // head dim
#define TD 768     // 3*D

// Scratch: qkv [B*S, 3D] fp32 (25.2 MB) — __device__ global, no allocation.
__device__ float g_qkv[BB * SS * TD];

// ---------------------------------------------------------------------------
// Kernel 1: x = news + pos ; qkv = x @ in_proj_w^T + in_proj_b
// GEMM M=8192 N=768 K=256. Tile 64x64, BK=16, 256 threads, 4x4 microtile.
// ---------------------------------------------------------------------------
#define K1_BM 64
#define K1_BN 64
#define K1_BK 16

__global__ __launch_bounds__(256) void qkv_kernel(
    const float* __restrict__ news,
    const float* __restrict__ pos,
    const float* __restrict__ w,     // [768,256] row-major
    const float* __restrict__ bias)  // [768]
{
    __shared__ __align__(16) float As[K1_BK][K1_BM];
    __shared__ __align__(16) float Bs[K1_BK][K1_BN];

    const int m0 = blockIdx.y * K1_BM;
    const int n0 = blockIdx.x * K1_BN;
    const int t  = threadIdx.x;

    const int lr  = t >> 2;          // 0..63
    const int lk4 = (t & 3) * 4;     // 0,4,8,12
    const int tx  = t & 15;
    const int ty  = t >> 4;

    float acc[4][4];
#pragma unroll
    for (int i = 0; i < 4; i++)
#pragma unroll
        for (int j = 0; j < 4; j++) acc[i][j] = 0.f;

    const int arow = m0 + lr;
    const int srow = arow & (SS - 1);
    const int brow = n0 + lr;

    for (int k0 = 0; k0 < DD; k0 += K1_BK) {
        // Load A tile (with fused pos add)
        float4 nv = *reinterpret_cast<const float4*>(news + (size_t)arow * DD + k0 + lk4);
        float4 pv = *reinterpret_cast<const float4*>(pos  + (size_t)srow * DD + k0 + lk4);
        As[lk4 + 0][lr] = nv.x + pv.x;
        As[lk4 + 1][lr] = nv.y + pv.y;
        As[lk4 + 2][lr] = nv.z + pv.z;
        As[lk4 + 3][lr] = nv.w + pv.w;
        // Load B tile
        float4 wv = *reinterpret_cast<const float4*>(w + (size_t)brow * DD + k0 + lk4);
        Bs[lk4 + 0][lr] = wv.x;
        Bs[lk4 + 1][lr] = wv.y;
        Bs[lk4 + 2][lr] = wv.z;
        Bs[lk4 + 3][lr] = wv.w;
        __syncthreads();

#pragma unroll
        for (int k = 0; k < K1_BK; k++) {
            float4 a4 = *reinterpret_cast<const float4*>(&As[k][ty * 4]);
            float4 b4 = *reinterpret_cast<const float4*>(&Bs[k][tx * 4]);
            float a[4] = {a4.x, a4.y, a4.z, a4.w};
            float b[4] = {b4.x, b4.y, b4.z, b4.w};
#pragma unroll
            for (int i = 0; i < 4; i++)
#pragma unroll
                for (int j = 0; j < 4; j++)
                    acc[i][j] = fmaf(a[i], b[j], acc[i][j]);
        }
        __syncthreads();
    }

    const int orow = m0 + ty * 4;
    const int ocol = n0 + tx * 4;
    float4 bv = *reinterpret_cast<const float4*>(bias + ocol);
#pragma unroll
    for (int i = 0; i < 4; i++) {
        float4 r;
        r.x = acc[i][0] + bv.x;
        r.y = acc[i][1] + bv.y;
        r.z = acc[i][2] + bv.z;
        r.w = acc[i][3] + bv.w;
        *reinterpret_cast<float4*>(g_qkv + (size_t)(orow + i) * TD + ocol) = r;
    }
}

// ---------------------------------------------------------------------------
// Kernel 2: scores = Q K^T / 4, causal + padding mask, softmax, write weights.
// One block = (b, h, 16 query rows). 256 threads: warp w owns rows 2w,2w+1;
// lane tk owns keys tk+32j (j=0..15). Warp-shuffle row reductions.
// ---------------------------------------------------------------------------
__global__ __launch_bounds__(256) void attn_kernel(
    const unsigned char* __restrict__ mask,   // [B,S] (bytes; all-zero dataset)
    float* __restrict__ wout)                 // [B,H,S,S]
{
    __shared__ __align__(16) float Kt[HD][SS + 4];   // transposed K, padded stride
    __shared__ unsigned char pm[SS];

    const int b  = blockIdx.z;
    const int h  = blockIdx.y;
    const int q0 = blockIdx.x * 16;
    const int t  = threadIdx.x;

    // Load K (transposed into smem)
    const float* kbase = g_qkv + (size_t)b * SS * TD + DD + h * HD;
    for (int idx = t; idx < SS * 4; idx += 256) {
        int key = idx >> 2;
        int dq  = (idx & 3) * 4;
        float4 kv = *reinterpret_cast<const float4*>(kbase + (size_t)key * TD + dq);
        Kt[dq + 0][key] = kv.x;
        Kt[dq + 1][key] = kv.y;
        Kt[dq + 2][key] = kv.z;
        Kt[dq + 3][key] = kv.w;
    }
    for (int idx = t; idx < SS; idx += 256) pm[idx] = mask[b * SS + idx];
    __syncthreads();

    const int tq = t >> 5;   // warp id 0..7
    const int tk = t & 31;
    const int r0 = q0 + 2 * tq;
    const int r1 = r0 + 1;

    // Load 2 query rows into registers (broadcast across warp — cheap)
    float qa[HD], qb[HD];
    const float* qrow = g_qkv + (size_t)(b * SS + r0) * TD + h * HD;
#pragma unroll
    for (int d4 = 0; d4 < 4; d4++) {
        float4 v0 = *reinterpret_cast<const float4*>(qrow + d4 * 4);
        float4 v1 = *reinterpret_cast<const float4*>(qrow + TD + d4 * 4);
        qa[d4 * 4 + 0] = v0.x; qa[d4 * 4 + 1] = v0.y; qa[d4 * 4 + 2] = v0.z; qa[d4 * 4 + 3] = v0.w;
        qb[d4 * 4 + 0] = v1.x; qb[d4 * 4 + 1] = v1.y; qb[d4 * 4 + 2] = v1.z; qb[d4 * 4 + 3] = v1.w;
    }

    float s0[16], s1[16];
#pragma unroll
    for (int j = 0; j < 16; j++) { s0[j] = 0.f; s1[j] = 0.f; }

#pragma unroll
    for (int d = 0; d < HD; d++) {
        float a0 = qa[d], a1 = qb[d];
#pragma unroll
        for (int j = 0; j < 16; j++) {
            float kv = Kt[d][tk + 32 * j];
            s0[j] = fmaf(a0, kv, s0[j]);
            s1[j] = fmaf(a1, kv, s1[j]);
        }
    }

    const float NEG = -CUDART_INF_F;
    float m0 = NEG, m1 = NEG;
#pragma unroll
    for (int j = 0; j < 16; j++) {
        int key = tk + 32 * j;
        bool pad = (pm[key] != 0);
        float v0 = (key > r0 || pad) ? NEG : s0[j] * 0.25f;
        float v1 = (key > r1 || pad) ? NEG : s1[j] * 0.25f;
        s0[j] = v0; s1[j] = v1;
        m0 = fmaxf(m0, v0); m1 = fmaxf(m1, v1);
    }
#pragma unroll
    for (int off = 16; off > 0; off >>= 1) {
        m0 = fmaxf(m0, __shfl_xor_sync(0xffffffffu, m0, off));
        m1 = fmaxf(m1, __shfl_xor_sync(0xffffffffu, m1, off));
    }

    float sum0 = 0.f, sum1 = 0.f;
#pragma unroll
    for (int j = 0; j < 16; j++) {
        float e0 = __expf(s0[j] - m0);
        float e1 = __expf(s1[j] - m1);
        s0[j] = e0; s1[j] = e1;
        sum0 += e0; sum1 += e1;
    }
#pragma unroll
    for (int off = 16; off > 0; off >>= 1) {
        sum0 += __shfl_xor_sync(0xffffffffu, sum0, off);
        sum1 += __shfl_xor_sync(0xffffffffu, sum1, off);
    }
    float inv0 = 1.f / sum0;
    float inv1 = 1.f / sum1;

    float* o0 = wout + (((size_t)(b * HH + h) * SS + r0) * SS);
    float* o1 = o0 + SS;
#pragma unroll
    for (int j = 0; j < 16; j++) {
        o0[tk + 32 * j] = s0[j] * inv0;
        o1[tk + 32 * j] = s1[j] * inv1;
    }
}

// ---------------------------------------------------------------------------
// Kernel 3: per-batch epilogue at last non-padded position only.
// attn@V (1 row), out_proj, proj, LayerNorm, ReLU, L2-normalize.
// ---------------------------------------------------------------------------
__device__ __forceinline__ float block_reduce_sum(float v, float* red, int t) {
    red[t] = v;
    __syncthreads();
#pragma unroll
    for (int off = 128; off > 0; off >>= 1) {
        if (t < off) red[t] += red[t + off];
        __syncthreads();
    }
    float r = red[0];
    __syncthreads();
    return r;
}

__global__ __launch_bounds__(256) void user_kernel(
    const unsigned char* __restrict__ mask,
    const float* __restrict__ wfull,    // attn_weights [B,H,S,S]
    const float* __restrict__ outw, const float* __restrict__ outb,
    const float* __restrict__ projw, const float* __restrict__ projb,
    const float* __restrict__ lng, const float* __restrict__ lnb,
    float* __restrict__ user)           // [B,D]
{
    __shared__ float wsm[HH][SS];   // 32 KB
    __shared__ float av[DD];
    __shared__ float h1[DD];
    __shared__ float red[256];
    __shared__ int s_last;

    const int b = blockIdx.x;
    const int t = threadIdx.x;

    // seq length / last index
    int cnt = 0;
    for (int s = t; s < SS; s += 256) cnt += (mask[b * SS + s] == 0) ? 1 : 0;
    float lenf = block_reduce_sum((float)cnt, red, t);
    if (t == 0) {
        int len = (int)(lenf + 0.5f);
        s_last = (len > 0) ? (len - 1) : 0;
    }
    __syncthreads();
    const int last = s_last;

    // Load attention weight rows for all heads at last position
    for (int idx = t; idx < HH * SS; idx += 256) {
        int hh = idx >> 9;
        int k  = idx & (SS - 1);
        wsm[hh][k] = wfull[(((size_t)(b * HH + hh) * SS + last) * SS) + k];
    }
    __syncthreads();

    // attn vector: av[d] = sum_k w[h(d),k] * v[k,d]
    {
        const int hh = t >> 4;
        const float* vbase = g_qkv + (size_t)b * SS * TD + 2 * DD + t;
        float acc = 0.f;
        for (int k = 0; k < SS; k++)
            acc = fmaf(wsm[hh][k], vbase[(size_t)k * TD], acc);
        av[t] = acc;
    }
    __syncthreads();

    // out projection
    {
        float acc = outb[t];
        const float* wr = outw + (size_t)t * DD;
        for (int i = 0; i < DD; i++) acc = fmaf(av[i], wr[i], acc);
        h1[t] = acc;
    }
    __syncthreads();

    // proj
    float hv;
    {
        float acc = projb[t];
        const float* wr = projw + (size_t)t * DD;
        for (int i = 0; i < DD; i++) acc = fmaf(h1[i], wr[i], acc);
        hv = acc;
    }

    // LayerNorm + ReLU
    float mu = block_reduce_sum(hv, red, t) * (1.0f / DD);
    float c  = hv - mu;
    float var = block_reduce_sum(c * c, red, t) * (1.0f / DD);
    float y = c * rsqrtf(var + 1e-5f) * lng[t] + lnb[t];
    y = fmaxf(y, 0.f);

    // L2 normalize
    float ss = block_reduce_sum(y * y, red, t);
    float norm = sqrtf(ss);
    float denom = fmaxf(norm, 1e-12f);
    user[b * DD + t] = y / denom;
}

// ---------------------------------------------------------------------------
extern "C" void kernel_launch(void* const* d_in, const int* in_sizes, int n_in,
                              void* d_out, int out_size) {
    const float*         news  = (const float*)d_in[0];
    const unsigned char* mask  = (const unsigned char*)d_in[1];
    const float*         pos   = (const float*)d_in[2];
    const float*         inw   = (const float*)d_in[3];
    const float*         inb   = (const float*)d_in[4];
    const float*         outw  = (const float*)d_in[5];
    const float*         outb  = (const float*)d_in[6];
    const float*         projw = (const float*)d_in[7];
    const float*         projb = (const float*)d_in[8];
    const float*         lng   = (const float*)d_in[9];
    const float*         lnb   = (const float*)d_in[10];

    float* user = (float*)d_out;                 // [B,D] first in tuple order
    float* wout = (float*)d_out + (BB * DD);     // attn_weights [B,H,S,S]

    // 1. QKV projection (fused positional add)
    {
        dim3 grid(TD / K1_BN, (BB * SS) / K1_BM);
        qkv_kernel<<<grid, 256>>>(news, pos, inw, inb);
    }
    // 2. Attention scores + softmax + weight output
    {
        dim3 grid(SS / 16, HH, BB);
        attn_kernel<<<grid, 256>>>(mask, wout);
    }
    // 3. Per-batch epilogue -> user embedding
    {
        user_kernel<<<BB, 256>>>(mask, wout, outw, outb, projw, projb, lng, lnb, user);
    }
}

// round 2
// speedup vs baseline: 1.4640x; 1.4640x over previous
#include <cuda_runtime.h>
#include <math_constants.h>
#include <cstdint>

#define BB 16
#define SS 512
#define DD 256
#define HH 16
#define HD 16
#define TD 768

typedef unsigned long long ull;

__device__ float g_qkv[BB * SS * TD];   // scratch qkv [B*S, 3D]

// ---- packed f32x2 helpers (Blackwell FFMA2 path) ----
__device__ __forceinline__ ull pack2(float x, float y) {
    ull r;
    asm("mov.b64 %0, {%1, %2};" : "=l"(r) : "f"(x), "f"(y));
    return r;
}
__device__ __forceinline__ void unpack2(ull v, float& x, float& y) {
    asm("mov.b64 {%0, %1}, %2;" : "=f"(x), "=f"(y) : "l"(v));
}
__device__ __forceinline__ ull fma2(ull a, ull b, ull c) {
    ull d;
    asm("fma.rn.f32x2 %0, %1, %2, %3;" : "=l"(d) : "l"(a), "l"(b), "l"(c));
    return d;
}

// ---------------------------------------------------------------------------
// Kernel 1: qkv = (news + pos) @ in_proj_w^T + b
// M=8192 N=768 K=256. BM=128 BN=64 BK=16, 256 thr, 8x4 microtile, FFMA2.
// ---------------------------------------------------------------------------
__global__ __launch_bounds__(256) void qkv_kernel(
    const float* __restrict__ news,
    const float* __restrict__ pos,
    const float* __restrict__ w,
    const float* __restrict__ bias)
{
    __shared__ __align__(16) float As[16][128];
    __shared__ __align__(16) float Bs[16][64];

    const int t  = threadIdx.x;
    const int n0 = blockIdx.x * 64;
    const int m0 = blockIdx.y * 128;

    const int ar = t >> 1;          // 0..127  A row in tile
    const int ak = (t & 1) * 8;     // k offset 0 or 8
    const int br = t >> 2;          // 0..63   B row in tile
    const int bk = (t & 3) * 4;     // k offset 0,4,8,12

    const int tm = t >> 4;          // 0..15 -> 8 rows
    const int tn = t & 15;          // 0..15 -> 4 cols

    const float* aP = news + (size_t)(m0 + ar) * DD;
    const float* pP = pos  + (size_t)((m0 + ar) & (SS - 1)) * DD;
    const float* bP = w    + (size_t)(n0 + br) * DD;

    ull acc[4][4];
#pragma unroll
    for (int i = 0; i < 4; i++)
#pragma unroll
        for (int j = 0; j < 4; j++) acc[i][j] = 0ULL;

    // prefetch tile 0
    float4 ra0, ra1, rb0;
    {
        float4 n0v = *reinterpret_cast<const float4*>(aP + ak);
        float4 n1v = *reinterpret_cast<const float4*>(aP + ak + 4);
        float4 p0v = *reinterpret_cast<const float4*>(pP + ak);
        float4 p1v = *reinterpret_cast<const float4*>(pP + ak + 4);
        ra0.x = n0v.x + p0v.x; ra0.y = n0v.y + p0v.y; ra0.z = n0v.z + p0v.z; ra0.w = n0v.w + p0v.w;
        ra1.x = n1v.x + p1v.x; ra1.y = n1v.y + p1v.y; ra1.z = n1v.z + p1v.z; ra1.w = n1v.w + p1v.w;
        rb0 = *reinterpret_cast<const float4*>(bP + bk);
    }

    for (int k0 = 0; k0 < DD; k0 += 16) {
        As[ak + 0][ar] = ra0.x; As[ak + 1][ar] = ra0.y; As[ak + 2][ar] = ra0.z; As[ak + 3][ar] = ra0.w;
        As[ak + 4][ar] = ra1.x; As[ak + 5][ar] = ra1.y; As[ak + 6][ar] = ra1.z; As[ak + 7][ar] = ra1.w;
        Bs[bk + 0][br] = rb0.x; Bs[bk + 1][br] = rb0.y; Bs[bk + 2][br] = rb0.z; Bs[bk + 3][br] = rb0.w;
        __syncthreads();

        if (k0 + 16 < DD) {
            int kn = k0 + 16;
            float4 n0v = *reinterpret_cast<const float4*>(aP + kn + ak);
            float4 n1v = *reinterpret_cast<const float4*>(aP + kn + ak + 4);
            float4 p0v = *reinterpret_cast<const float4*>(pP + kn + ak);
            float4 p1v = *reinterpret_cast<const float4*>(pP + kn + ak + 4);
            ra0.x = n0v.x + p0v.x; ra0.y = n0v.y + p0v.y; ra0.z = n0v.z + p0v.z; ra0.w = n0v.w + p0v.w;
            ra1.x = n1v.x + p1v.x; ra1.y = n1v.y + p1v.y; ra1.z = n1v.z + p1v.z; ra1.w = n1v.w + p1v.w;
            rb0 = *reinterpret_cast<const float4*>(bP + kn + bk);
        }

#pragma unroll
        for (int k = 0; k < 16; k++) {
            const ull* ap = reinterpret_cast<const ull*>(&As[k][tm * 8]);
            ull a0 = ap[0], a1 = ap[1], a2 = ap[2], a3 = ap[3];
            float4 b4 = *reinterpret_cast<const float4*>(&Bs[k][tn * 4]);
            ull b0 = pack2(b4.x, b4.x);
            ull b1 = pack2(b4.y, b4.y);
            ull b2 = pack2(b4.z, b4.z);
            ull b3 = pack2(b4.w, b4.w);
            acc[0][0] = fma2(a0, b0, acc[0][0]); acc[0][1] = fma2(a0, b1, acc[0][1]);
            acc[0][2] = fma2(a0, b2, acc[0][2]); acc[0][3] = fma2(a0, b3, acc[0][3]);
            acc[1][0] = fma2(a1, b0, acc[1][0]); acc[1][1] = fma2(a1, b1, acc[1][1]);
            acc[1][2] = fma2(a1, b2, acc[1][2]); acc[1][3] = fma2(a1, b3, acc[1][3]);
            acc[2][0] = fma2(a2, b0, acc[2][0]); acc[2][1] = fma2(a2, b1, acc[2][1]);
            acc[2][2] = fma2(a2, b2, acc[2][2]); acc[2][3] = fma2(a2, b3, acc[2][3]);
            acc[3][0] = fma2(a3, b0, acc[3][0]); acc[3][1] = fma2(a3, b1, acc[3][1]);
            acc[3][2] = fma2(a3, b2, acc[3][2]); acc[3][3] = fma2(a3, b3, acc[3][3]);
        }
        __syncthreads();
    }

    const int ocol = n0 + tn * 4;
    float4 bv = *reinterpret_cast<const float4*>(bias + ocol);
#pragma unroll
    for (int mp = 0; mp < 4; mp++) {
        float lo0, hi0, lo1, hi1, lo2, hi2, lo3, hi3;
        unpack2(acc[mp][0], lo0, hi0);
        unpack2(acc[mp][1], lo1, hi1);
        unpack2(acc[mp][2], lo2, hi2);
        unpack2(acc[mp][3], lo3, hi3);
        int r0 = m0 + tm * 8 + 2 * mp;
        float4 v0 = {lo0 + bv.x, lo1 + bv.y, lo2 + bv.z, lo3 + bv.w};
        float4 v1 = {hi0 + bv.x, hi1 + bv.y, hi2 + bv.z, hi3 + bv.w};
        *reinterpret_cast<float4*>(g_qkv + (size_t)r0 * TD + ocol)       = v0;
        *reinterpret_cast<float4*>(g_qkv + (size_t)(r0 + 1) * TD + ocol) = v1;
    }
}

// ---------------------------------------------------------------------------
// Kernel 2: scores + causal/pad mask + softmax -> attn_weights.
// Block = (b, h, 32 q rows). Skips key-blocks fully above the diagonal.
// Warp owns 4 rows; lane owns 4 consecutive keys per 128-key block. FFMA2.
// ---------------------------------------------------------------------------
__global__ __launch_bounds__(256) void attn_kernel(
    const unsigned char* __restrict__ mask,
    float* __restrict__ wout)
{
    __shared__ __align__(16) float Kt[HD][516];
    __shared__ float Qs[32][HD];
    __shared__ __align__(4) unsigned char pm[SS];

    const int b  = blockIdx.z;
    const int h  = blockIdx.y;
    const int q0 = blockIdx.x * 32;
    const int t  = threadIdx.x;

    const int njb   = (q0 + 32 + 127) >> 7;   // key blocks needed (1..4)
    const int kmaxL = njb << 7;

    const float* kbase = g_qkv + (size_t)b * SS * TD + DD + h * HD;
    for (int idx = t; idx < kmaxL * 4; idx += 256) {
        int key = idx >> 2;
        int dq  = (idx & 3) * 4;
        float4 kv = *reinterpret_cast<const float4*>(kbase + (size_t)key * TD + dq);
        Kt[dq + 0][key] = kv.x;
        Kt[dq + 1][key] = kv.y;
        Kt[dq + 2][key] = kv.z;
        Kt[dq + 3][key] = kv.w;
    }
    if (t < 128) {
        int row = t >> 2;
        int dq  = (t & 3) * 4;
        float4 qv = *reinterpret_cast<const float4*>(
            g_qkv + (size_t)(b * SS + q0 + row) * TD + h * HD + dq);
        Qs[row][dq + 0] = qv.x; Qs[row][dq + 1] = qv.y;
        Qs[row][dq + 2] = qv.z; Qs[row][dq + 3] = qv.w;
    }
    for (int idx = t; idx < kmaxL; idx += 256) pm[idx] = mask[b * SS + idx];
    __syncthreads();

    const int wd    = t >> 5;
    const int lane  = t & 31;
    const int rbase = 4 * wd;

    ull s2[4][2][4];
#pragma unroll
    for (int r = 0; r < 4; r++)
#pragma unroll
        for (int p = 0; p < 2; p++)
#pragma unroll
            for (int jb = 0; jb < 4; jb++) s2[r][p][jb] = 0ULL;

#pragma unroll
    for (int d = 0; d < HD; d++) {
        ull q2[4];
#pragma unroll
        for (int r = 0; r < 4; r++) {
            float qv = Qs[rbase + r][d];
            q2[r] = pack2(qv, qv);
        }
#pragma unroll
        for (int jb = 0; jb < 4; jb++) {
            if (jb < njb) {
                const ull* kp = reinterpret_cast<const ull*>(&Kt[d][4 * lane + 128 * jb]);
                ull k0 = kp[0], k1 = kp[1];
#pragma unroll
                for (int r = 0; r < 4; r++) {
                    s2[r][0][jb] = fma2(q2[r], k0, s2[r][0][jb]);
                    s2[r][1][jb] = fma2(q2[r], k1, s2[r][1][jb]);
                }
            }
        }
    }

    const float NEG = -CUDART_INF_F;
#pragma unroll
    for (int r = 0; r < 4; r++) {
        const int rg = q0 + rbase + r;
        float v[16];
#pragma unroll
        for (int jb = 0; jb < 4; jb++) {
            if (jb < njb) {
                int kb = 4 * lane + 128 * jb;
                uchar4 pmv = *reinterpret_cast<const uchar4*>(&pm[kb]);
                float f0, f1, f2, f3;
                unpack2(s2[r][0][jb], f0, f1);
                unpack2(s2[r][1][jb], f2, f3);
                v[jb * 4 + 0] = (kb + 0 > rg || pmv.x) ? NEG : f0 * 0.25f;
                v[jb * 4 + 1] = (kb + 1 > rg || pmv.y) ? NEG : f1 * 0.25f;
                v[jb * 4 + 2] = (kb + 2 > rg || pmv.z) ? NEG : f2 * 0.25f;
                v[jb * 4 + 3] = (kb + 3 > rg || pmv.w) ? NEG : f3 * 0.25f;
            } else {
                v[jb * 4 + 0] = NEG; v[jb * 4 + 1] = NEG;
                v[jb * 4 + 2] = NEG; v[jb * 4 + 3] = NEG;
            }
        }
        float m = NEG;
#pragma unroll
        for (int j = 0; j < 16; j++) m = fmaxf(m, v[j]);
#pragma unroll
        for (int off = 16; off > 0; off >>= 1)
            m = fmaxf(m, __shfl_xor_sync(0xffffffffu, m, off));
        float sum = 0.f;
#pragma unroll
        for (int j = 0; j < 16; j++) { v[j] = __expf(v[j] - m); sum += v[j]; }
#pragma unroll
        for (int off = 16; off > 0; off >>= 1)
            sum += __shfl_xor_sync(0xffffffffu, sum, off);
        float inv = 1.f / sum;

        float4* orow = reinterpret_cast<float4*>(
            wout + (((size_t)(b * HH + h) * SS + rg) * SS));
#pragma unroll
        for (int jb = 0; jb < 4; jb++) {
            float4 o;
            if (jb < njb) {
                o.x = v[jb * 4 + 0] * inv;
                o.y = v[jb * 4 + 1] * inv;
                o.z = v[jb * 4 + 2] * inv;
                o.w = v[jb * 4 + 3] * inv;
            } else {
                o.x = 0.f; o.y = 0.f; o.z = 0.f; o.w = 0.f;
            }
            __stcs(orow + lane + 32 * jb, o);
        }
    }
}

// ---------------------------------------------------------------------------
// Kernel 3: per-batch epilogue at the last non-padded position.
// ---------------------------------------------------------------------------
__device__ __forceinline__ float block_reduce_sum(float v, float* red, int t) {
    red[t] = v;
    __syncthreads();
#pragma unroll
    for (int off = 128; off > 0; off >>= 1) {
        if (t < off) red[t] += red[t + off];
        __syncthreads();
    }
    float r = red[0];
    __syncthreads();
    return r;
}

__global__ __launch_bounds__(256) void user_kernel(
    const unsigned char* __restrict__ mask,
    const float* __restrict__ wfull,
    const float* __restrict__ outw, const float* __restrict__ outb,
    const float* __restrict__ projw, const float* __restrict__ projb,
    const float* __restrict__ lng, const float* __restrict__ lnb,
    float* __restrict__ user)
{
    __shared__ float wsm[HH][SS];
    __shared__ __align__(16) float av[DD];
    __shared__ __align__(16) float h1[DD];
    __shared__ float h2[DD];
    __shared__ float red[256];
    __shared__ int s_last;

    const int b = blockIdx.x;
    const int t = threadIdx.x;
    const int wd = t >> 5, lane = t & 31;

    int cnt = 0;
    for (int s = t; s < SS; s += 256) cnt += (mask[b * SS + s] == 0) ? 1 : 0;
    float lenf = block_reduce_sum((float)cnt, red, t);
    if (t == 0) {
        int len = (int)(lenf + 0.5f);
        s_last = (len > 0) ? (len - 1) : 0;
    }
    __syncthreads();
    const int last = s_last;

    for (int idx = t; idx < HH * SS; idx += 256) {
        int hh = idx >> 9;
        int k  = idx & (SS - 1);
        wsm[hh][k] = wfull[(((size_t)(b * HH + hh) * SS + last) * SS) + k];
    }
    __syncthreads();

    // attn vector av[d] = sum_k w[h(d),k] * V[k,d]
    {
        const int hh = t >> 4;
        const float* vb = g_qkv + (size_t)b * SS * TD + 2 * DD + t;
        float a0 = 0.f, a1 = 0.f, a2 = 0.f, a3 = 0.f;
        for (int k = 0; k < SS; k += 4) {
            a0 = fmaf(wsm[hh][k + 0], vb[(size_t)(k + 0) * TD], a0);
            a1 = fmaf(wsm[hh][k + 1], vb[(size_t)(k + 1) * TD], a1);
            a2 = fmaf(wsm[hh][k + 2], vb[(size_t)(k + 2) * TD], a2);
            a3 = fmaf(wsm[hh][k + 3], vb[(size_t)(k + 3) * TD], a3);
        }
        av[t] = (a0 + a1) + (a2 + a3);
    }
    __syncthreads();

    // out projection: warp-cooperative coalesced matvec
    {
        const float4* xp = reinterpret_cast<const float4*>(av);
        float4 x0 = xp[lane * 2], x1 = xp[lane * 2 + 1];
        for (int jj = 0; jj < 32; jj++) {
            int j = wd * 32 + jj;
            const float4* wr = reinterpret_cast<const float4*>(outw + (size_t)j * DD);
            float4 w0 = wr[lane * 2], w1 = wr[lane * 2 + 1];
            float acc = x0.x * w0.x + x0.y * w0.y + x0.z * w0.z + x0.w * w0.w
                      + x1.x * w1.x + x1.y * w1.y + x1.z * w1.z + x1.w * w1.w;
#pragma unroll
            for (int off = 16; off > 0; off >>= 1)
                acc += __shfl_xor_sync(0xffffffffu, acc, off);
            if (lane == 0) h1[j] = acc + outb[j];
        }
    }
    __syncthreads();

    // proj: warp-cooperative coalesced matvec
    {
        const float4* xp = reinterpret_cast<const float4*>(h1);
        float4 x0 = xp[lane * 2], x1 = xp[lane * 2 + 1];
        for (int jj = 0; jj < 32; jj++) {
            int j = wd * 32 + jj;
            const float4* wr = reinterpret_cast<const float4*>(projw + (size_t)j * DD);
            float4 w0 = wr[lane * 2], w1 = wr[lane * 2 + 1];
            float acc = x0.x * w0.x + x0.y * w0.y + x0.z * w0.z + x0.w * w0.w
                      + x1.x * w1.x + x1.y * w1.y + x1.z * w1.z + x1.w * w1.w;
#pragma unroll
            for (int off = 16; off > 0; off >>= 1)
                acc += __shfl_xor_sync(0xffffffffu, acc, off);
            if (lane == 0) h2[j] = acc + projb[j];
        }
    }
    __syncthreads();

    float hv = h2[t];
    float mu = block_reduce_sum(hv, red, t) * (1.0f / DD);
    float c  = hv - mu;
    float var = block_reduce_sum(c * c, red, t) * (1.0f / DD);
    float y = c * rsqrtf(var + 1e-5f) * lng[t] + lnb[t];
    y = fmaxf(y, 0.f);

    float ss = block_reduce_sum(y * y, red, t);
    float norm = sqrtf(ss);
    float denom = fmaxf(norm, 1e-12f);
    user[b * DD + t] = y / denom;
}

// ---------------------------------------------------------------------------
extern "C" void kernel_launch(void* const* d_in, const int* in_sizes, int n_in,
                              void* d_out, int out_size) {
    const float*         news  = (const float*)d_in[0];
    const unsigned char* mask  = (const unsigned char*)d_in[1];
    const float*         pos   = (const float*)d_in[2];
    const float*         inw   = (const float*)d_in[3];
    const float*         inb   = (const float*)d_in[4];
    const float*         outw  = (const float*)d_in[5];
    const float*         outb  = (const float*)d_in[6];
    const float*         projw = (const float*)d_in[7];
    const float*         projb = (const float*)d_in[8];
    const float*         lng   = (const float*)d_in[9];
    const float*         lnb   = (const float*)d_in[10];

    float* user = (float*)d_out;
    float* wout = (float*)d_out + (BB * DD);

    {
        dim3 grid(TD / 64, (BB * SS) / 128);
        qkv_kernel<<<grid, 256>>>(news, pos, inw, inb);
    }
    {
        dim3 grid(SS / 32, HH, BB);
        attn_kernel<<<grid, 256>>>(mask, wout);
    }
    {
        user_kernel<<<BB, 256>>>(mask, wout, outw, outb, projw, projb, lng, lnb, user);
    }
}

// round 3
// speedup vs baseline: 1.5013x; 1.0255x over previous
#include <cuda_runtime.h>
#include <math_constants.h>
#include <cstdint>

#define BB 16
#define SS 512
#define DD 256
#define HH 16
#define HD 16
#define TD 768

typedef unsigned long long ull;

__device__ float g_qkv[BB * SS * TD];   // scratch qkv [B*S, 3D]

__device__ __forceinline__ ull pack2(float x, float y) {
    ull r;
    asm("mov.b64 %0, {%1, %2};" : "=l"(r) : "f"(x), "f"(y));
    return r;
}
__device__ __forceinline__ void unpack2(ull v, float& x, float& y) {
    asm("mov.b64 {%0, %1}, %2;" : "=f"(x), "=f"(y) : "l"(v));
}
__device__ __forceinline__ ull fma2(ull a, ull b, ull c) {
    ull d;
    asm("fma.rn.f32x2 %0, %1, %2, %3;" : "=l"(d) : "l"(a), "l"(b), "l"(c));
    return d;
}

// padded B-column index: spread tn*8 chunks across all 32 banks
__device__ __forceinline__ int bpad(int c) { return c + ((c >> 5) << 2); }

// ---------------------------------------------------------------------------
// Kernel 1: qkv = (news + pos) @ in_proj_w^T + b
// M=8192 N=768 K=256. BM=128 BN=128 BK=16, 256 thr, 8x8 microtile, FFMA2.
// ---------------------------------------------------------------------------
__global__ __launch_bounds__(256, 2) void qkv_kernel(
    const float* __restrict__ news,
    const float* __restrict__ pos,
    const float* __restrict__ w,
    const float* __restrict__ bias)
{
    __shared__ __align__(16) float As[16][128];
    __shared__ __align__(16) float Bs[16][144];   // padded: 128 cols + 4 per 32

    const int t  = threadIdx.x;
    const int n0 = blockIdx.x * 128;
    const int m0 = blockIdx.y * 128;

    const int ar = t >> 1;           // 0..127
    const int ak = (t & 1) * 8;      // 0 or 8
    const int br = ar;
    const int bk = ak;
    const int brp = bpad(br);        // padded store col (scalar stores)

    const int tm = t >> 4;           // 0..15 -> 8 rows
    const int tn = t & 15;           // 0..15 -> 8 cols
    const int bload = bpad(tn * 8);  // padded read base (contiguous 8)

    const float* aP = news + (size_t)(m0 + ar) * DD;
    const float* pP = pos  + (size_t)((m0 + ar) & (SS - 1)) * DD;
    const float* bP = w    + (size_t)(n0 + br) * DD;

    ull acc[4][8];
#pragma unroll
    for (int i = 0; i < 4; i++)
#pragma unroll
        for (int j = 0; j < 8; j++) acc[i][j] = 0ULL;

    float4 ra0, ra1, rb0, rb1;
    {
        float4 n0v = *reinterpret_cast<const float4*>(aP + ak);
        float4 n1v = *reinterpret_cast<const float4*>(aP + ak + 4);
        float4 p0v = *reinterpret_cast<const float4*>(pP + ak);
        float4 p1v = *reinterpret_cast<const float4*>(pP + ak + 4);
        ra0.x = n0v.x + p0v.x; ra0.y = n0v.y + p0v.y; ra0.z = n0v.z + p0v.z; ra0.w = n0v.w + p0v.w;
        ra1.x = n1v.x + p1v.x; ra1.y = n1v.y + p1v.y; ra1.z = n1v.z + p1v.z; ra1.w = n1v.w + p1v.w;
        rb0 = *reinterpret_cast<const float4*>(bP + bk);
        rb1 = *reinterpret_cast<const float4*>(bP + bk + 4);
    }

    for (int k0 = 0; k0 < DD; k0 += 16) {
        As[ak + 0][ar] = ra0.x; As[ak + 1][ar] = ra0.y; As[ak + 2][ar] = ra0.z; As[ak + 3][ar] = ra0.w;
        As[ak + 4][ar] = ra1.x; As[ak + 5][ar] = ra1.y; As[ak + 6][ar] = ra1.z; As[ak + 7][ar] = ra1.w;
        Bs[bk + 0][brp] = rb0.x; Bs[bk + 1][brp] = rb0.y; Bs[bk + 2][brp] = rb0.z; Bs[bk + 3][brp] = rb0.w;
        Bs[bk + 4][brp] = rb1.x; Bs[bk + 5][brp] = rb1.y; Bs[bk + 6][brp] = rb1.z; Bs[bk + 7][brp] = rb1.w;
        __syncthreads();

        if (k0 + 16 < DD) {
            int kn = k0 + 16;
            float4 n0v = *reinterpret_cast<const float4*>(aP + kn + ak);
            float4 n1v = *reinterpret_cast<const float4*>(aP + kn + ak + 4);
            float4 p0v = *reinterpret_cast<const float4*>(pP + kn + ak);
            float4 p1v = *reinterpret_cast<const float4*>(pP + kn + ak + 4);
            ra0.x = n0v.x + p0v.x; ra0.y = n0v.y + p0v.y; ra0.z = n0v.z + p0v.z; ra0.w = n0v.w + p0v.w;
            ra1.x = n1v.x + p1v.x; ra1.y = n1v.y + p1v.y; ra1.z = n1v.z + p1v.z; ra1.w = n1v.w + p1v.w;
            rb0 = *reinterpret_cast<const float4*>(bP + kn + bk);
            rb1 = *reinterpret_cast<const float4*>(bP + kn + bk + 4);
        }

#pragma unroll
        for (int k = 0; k < 16; k++) {
            const ull* ap = reinterpret_cast<const ull*>(&As[k][tm * 8]);
            ull a0 = ap[0], a1 = ap[1], a2 = ap[2], a3 = ap[3];
            float4 b4a = *reinterpret_cast<const float4*>(&Bs[k][bload]);
            float4 b4b = *reinterpret_cast<const float4*>(&Bs[k][bload + 4]);
            ull b[8];
            b[0] = pack2(b4a.x, b4a.x); b[1] = pack2(b4a.y, b4a.y);
            b[2] = pack2(b4a.z, b4a.z); b[3] = pack2(b4a.w, b4a.w);
            b[4] = pack2(b4b.x, b4b.x); b[5] = pack2(b4b.y, b4b.y);
            b[6] = pack2(b4b.z, b4b.z); b[7] = pack2(b4b.w, b4b.w);
#pragma unroll
            for (int j = 0; j < 8; j++) {
                acc[0][j] = fma2(a0, b[j], acc[0][j]);
                acc[1][j] = fma2(a1, b[j], acc[1][j]);
                acc[2][j] = fma2(a2, b[j], acc[2][j]);
                acc[3][j] = fma2(a3, b[j], acc[3][j]);
            }
        }
        __syncthreads();
    }

    const int ocol = n0 + tn * 8;
    float4 bv0 = *reinterpret_cast<const float4*>(bias + ocol);
    float4 bv1 = *reinterpret_cast<const float4*>(bias + ocol + 4);
#pragma unroll
    for (int mp = 0; mp < 4; mp++) {
        float lo[8], hi[8];
#pragma unroll
        for (int j = 0; j < 8; j++) unpack2(acc[mp][j], lo[j], hi[j]);
        int r0 = m0 + tm * 8 + 2 * mp;
        float4 v0a = {lo[0] + bv0.x, lo[1] + bv0.y, lo[2] + bv0.z, lo[3] + bv0.w};
        float4 v0b = {lo[4] + bv1.x, lo[5] + bv1.y, lo[6] + bv1.z, lo[7] + bv1.w};
        float4 v1a = {hi[0] + bv0.x, hi[1] + bv0.y, hi[2] + bv0.z, hi[3] + bv0.w};
        float4 v1b = {hi[4] + bv1.x, hi[5] + bv1.y, hi[6] + bv1.z, hi[7] + bv1.w};
        float* o0 = g_qkv + (size_t)r0 * TD + ocol;
        *reinterpret_cast<float4*>(o0)          = v0a;
        *reinterpret_cast<float4*>(o0 + 4)      = v0b;
        *reinterpret_cast<float4*>(o0 + TD)     = v1a;
        *reinterpret_cast<float4*>(o0 + TD + 4) = v1b;
    }
}

// ---------------------------------------------------------------------------
// Kernel 2: scores + causal/pad mask + softmax -> attn_weights.
// Block = (b, h, 64 q rows), 512 threads. Warp owns 4 rows; lane owns 4
// consecutive keys per 128-key block. Skips blocks above causal diagonal.
// ---------------------------------------------------------------------------
__global__ __launch_bounds__(512) void attn_kernel(
    const unsigned char* __restrict__ mask,
    float* __restrict__ wout)
{
    __shared__ __align__(16) float Kt[HD][516];
    __shared__ float Qs[64][HD];
    __shared__ __align__(4) unsigned char pm[SS];

    const int b  = blockIdx.z;
    const int h  = blockIdx.y;
    const int q0 = blockIdx.x * 64;
    const int t  = threadIdx.x;

    const int njb   = (q0 + 64 + 127) >> 7;   // key blocks needed (1..4)
    const int kmaxL = njb << 7;

    const float* kbase = g_qkv + (size_t)b * SS * TD + DD + h * HD;
    for (int idx = t; idx < kmaxL * 4; idx += 512) {
        int key = idx >> 2;
        int dq  = (idx & 3) * 4;
        float4 kv = *reinterpret_cast<const float4*>(kbase + (size_t)key * TD + dq);
        Kt[dq + 0][key] = kv.x;
        Kt[dq + 1][key] = kv.y;
        Kt[dq + 2][key] = kv.z;
        Kt[dq + 3][key] = kv.w;
    }
    if (t < 256) {
        int row = t >> 2;
        int dq  = (t & 3) * 4;
        float4 qv = *reinterpret_cast<const float4*>(
            g_qkv + (size_t)(b * SS + q0 + row) * TD + h * HD + dq);
        Qs[row][dq + 0] = qv.x; Qs[row][dq + 1] = qv.y;
        Qs[row][dq + 2] = qv.z; Qs[row][dq + 3] = qv.w;
    }
    for (int idx = t; idx < kmaxL; idx += 512) pm[idx] = mask[b * SS + idx];
    __syncthreads();

    const int wd    = t >> 5;    // 0..15
    const int lane  = t & 31;
    const int rbase = 4 * wd;

    ull s2[4][2][4];
#pragma unroll
    for (int r = 0; r < 4; r++)
#pragma unroll
        for (int p = 0; p < 2; p++)
#pragma unroll
            for (int jb = 0; jb < 4; jb++) s2[r][p][jb] = 0ULL;

#pragma unroll
    for (int d = 0; d < HD; d++) {
        ull q2[4];
#pragma unroll
        for (int r = 0; r < 4; r++) {
            float qv = Qs[rbase + r][d];
            q2[r] = pack2(qv, qv);
        }
#pragma unroll
        for (int jb = 0; jb < 4; jb++) {
            if (jb < njb) {
                const ull* kp = reinterpret_cast<const ull*>(&Kt[d][4 * lane + 128 * jb]);
                ull k0 = kp[0], k1 = kp[1];
#pragma unroll
                for (int r = 0; r < 4; r++) {
                    s2[r][0][jb] = fma2(q2[r], k0, s2[r][0][jb]);
                    s2[r][1][jb] = fma2(q2[r], k1, s2[r][1][jb]);
                }
            }
        }
    }

    const float NEG = -CUDART_INF_F;
#pragma unroll
    for (int r = 0; r < 4; r++) {
        const int rg = q0 + rbase + r;
        float v[16];
#pragma unroll
        for (int jb = 0; jb < 4; jb++) {
            if (jb < njb) {
                int kb = 4 * lane + 128 * jb;
                uchar4 pmv = *reinterpret_cast<const uchar4*>(&pm[kb]);
                float f0, f1, f2, f3;
                unpack2(s2[r][0][jb], f0, f1);
                unpack2(s2[r][1][jb], f2, f3);
                v[jb * 4 + 0] = (kb + 0 > rg || pmv.x) ? NEG : f0 * 0.25f;
                v[jb * 4 + 1] = (kb + 1 > rg || pmv.y) ? NEG : f1 * 0.25f;
                v[jb * 4 + 2] = (kb + 2 > rg || pmv.z) ? NEG : f2 * 0.25f;
                v[jb * 4 + 3] = (kb + 3 > rg || pmv.w) ? NEG : f3 * 0.25f;
            } else {
                v[jb * 4 + 0] = NEG; v[jb * 4 + 1] = NEG;
                v[jb * 4 + 2] = NEG; v[jb * 4 + 3] = NEG;
            }
        }
        float m = NEG;
#pragma unroll
        for (int j = 0; j < 16; j++) m = fmaxf(m, v[j]);
#pragma unroll
        for (int off = 16; off > 0; off >>= 1)
            m = fmaxf(m, __shfl_xor_sync(0xffffffffu, m, off));
        float sum = 0.f;
#pragma unroll
        for (int j = 0; j < 16; j++) { v[j] = __expf(v[j] - m); sum += v[j]; }
#pragma unroll
        for (int off = 16; off > 0; off >>= 1)
            sum += __shfl_xor_sync(0xffffffffu, sum, off);
        float inv = 1.f / sum;

        float4* orow = reinterpret_cast<float4*>(
            wout + (((size_t)(b * HH + h) * SS + rg) * SS));
#pragma unroll
        for (int jb = 0; jb < 4; jb++) {
            float4 o;
            if (jb < njb) {
                o.x = v[jb * 4 + 0] * inv;
                o.y = v[jb * 4 + 1] * inv;
                o.z = v[jb * 4 + 2] * inv;
                o.w = v[jb * 4 + 3] * inv;
            } else {
                o.x = 0.f; o.y = 0.f; o.z = 0.f; o.w = 0.f;
            }
            __stcs(orow + lane + 32 * jb, o);
        }
    }
}

// ---------------------------------------------------------------------------
// Kernel 3: per-batch epilogue at the last non-padded position.
// ---------------------------------------------------------------------------
__device__ __forceinline__ float block_reduce_sum(float v, float* red, int t) {
    red[t] = v;
    __syncthreads();
#pragma unroll
    for (int off = 128; off > 0; off >>= 1) {
        if (t < off) red[t] += red[t + off];
        __syncthreads();
    }
    float r = red[0];
    __syncthreads();
    return r;
}

__global__ __launch_bounds__(256) void user_kernel(
    const unsigned char* __restrict__ mask,
    const float* __restrict__ wfull,
    const float* __restrict__ outw, const float* __restrict__ outb,
    const float* __restrict__ projw, const float* __restrict__ projb,
    const float* __restrict__ lng, const float* __restrict__ lnb,
    float* __restrict__ user)
{
    __shared__ float wsm[HH][SS];
    __shared__ __align__(16) float av[DD];
    __shared__ __align__(16) float h1[DD];
    __shared__ float h2[DD];
    __shared__ float red[256];
    __shared__ int s_last;

    const int b = blockIdx.x;
    const int t = threadIdx.x;
    const int wd = t >> 5, lane = t & 31;

    int cnt = 0;
    for (int s = t; s < SS; s += 256) cnt += (mask[b * SS + s] == 0) ? 1 : 0;
    float lenf = block_reduce_sum((float)cnt, red, t);
    if (t == 0) {
        int len = (int)(lenf + 0.5f);
        s_last = (len > 0) ? (len - 1) : 0;
    }
    __syncthreads();
    const int last = s_last;

    for (int idx = t; idx < HH * SS; idx += 256) {
        int hh = idx >> 9;
        int k  = idx & (SS - 1);
        wsm[hh][k] = wfull[(((size_t)(b * HH + hh) * SS + last) * SS) + k];
    }
    __syncthreads();

    // attn vector av[d] = sum_k w[h(d),k] * V[k,d]  (coalesced across t)
    {
        const int hh = t >> 4;
        const float* vb = g_qkv + (size_t)b * SS * TD + 2 * DD + t;
        float a[8];
#pragma unroll
        for (int i = 0; i < 8; i++) a[i] = 0.f;
        for (int k = 0; k < SS; k += 8) {
#pragma unroll
            for (int i = 0; i < 8; i++)
                a[i] = fmaf(wsm[hh][k + i], vb[(size_t)(k + i) * TD], a[i]);
        }
        av[t] = ((a[0] + a[1]) + (a[2] + a[3])) + ((a[4] + a[5]) + (a[6] + a[7]));
    }
    __syncthreads();

    // out projection: warp-cooperative coalesced matvec
    {
        const float4* xp = reinterpret_cast<const float4*>(av);
        float4 x0 = xp[lane * 2], x1 = xp[lane * 2 + 1];
        for (int jj = 0; jj < 32; jj++) {
            int j = wd * 32 + jj;
            const float4* wr = reinterpret_cast<const float4*>(outw + (size_t)j * DD);
            float4 w0 = wr[lane * 2], w1 = wr[lane * 2 + 1];
            float acc = x0.x * w0.x + x0.y * w0.y + x0.z * w0.z + x0.w * w0.w
                      + x1.x * w1.x + x1.y * w1.y + x1.z * w1.z + x1.w * w1.w;
#pragma unroll
            for (int off = 16; off > 0; off >>= 1)
                acc += __shfl_xor_sync(0xffffffffu, acc, off);
            if (lane == 0) h1[j] = acc + outb[j];
        }
    }
    __syncthreads();

    // proj: warp-cooperative coalesced matvec
    {
        const float4* xp = reinterpret_cast<const float4*>(h1);
        float4 x0 = xp[lane * 2], x1 = xp[lane * 2 + 1];
        for (int jj = 0; jj < 32; jj++) {
            int j = wd * 32 + jj;
            const float4* wr = reinterpret_cast<const float4*>(projw + (size_t)j * DD);
            float4 w0 = wr[lane * 2], w1 = wr[lane * 2 + 1];
            float acc = x0.x * w0.x + x0.y * w0.y + x0.z * w0.z + x0.w * w0.w
                      + x1.x * w1.x + x1.y * w1.y + x1.z * w1.z + x1.w * w1.w;
#pragma unroll
            for (int off = 16; off > 0; off >>= 1)
                acc += __shfl_xor_sync(0xffffffffu, acc, off);
            if (lane == 0) h2[j] = acc + projb[j];
        }
    }
    __syncthreads();

    float hv = h2[t];
    float mu = block_reduce_sum(hv, red, t) * (1.0f / DD);
    float c  = hv - mu;
    float var = block_reduce_sum(c * c, red, t) * (1.0f / DD);
    float y = c * rsqrtf(var + 1e-5f) * lng[t] + lnb[t];
    y = fmaxf(y, 0.f);

    float ss = block_reduce_sum(y * y, red, t);
    float norm = sqrtf(ss);
    float denom = fmaxf(norm, 1e-12f);
    user[b * DD + t] = y / denom;
}

// ---------------------------------------------------------------------------
extern "C" void kernel_launch(void* const* d_in, const int* in_sizes, int n_in,
                              void* d_out, int out_size) {
    const float*         news  = (const float*)d_in[0];
    const unsigned char* mask  = (const unsigned char*)d_in[1];
    const float*         pos   = (const float*)d_in[2];
    const float*         inw   = (const float*)d_in[3];
    const float*         inb   = (const float*)d_in[4];
    const float*         outw  = (const float*)d_in[5];
    const float*         outb  = (const float*)d_in[6];
    const float*         projw = (const float*)d_in[7];
    const float*         projb = (const float*)d_in[8];
    const float*         lng   = (const float*)d_in[9];
    const float*         lnb   = (const float*)d_in[10];

    float* user = (float*)d_out;
    float* wout = (float*)d_out + (BB * DD);

    {
        dim3 grid(TD / 128, (BB * SS) / 128);
        qkv_kernel<<<grid, 256>>>(news, pos, inw, inb);
    }
    {
        dim3 grid(SS / 64, HH, BB);
        attn_kernel<<<grid, 512>>>(mask, wout);
    }
    {
        user_kernel<<<BB, 256>>>(mask, wout, outw, outb, projw, projb, lng, lnb, user);
    }
}